// round 11
// baseline (speedup 1.0000x reference)
#include <cuda_runtime.h>
#include <cuda_fp16.h>
#include <cstdint>

#define DI __device__ __forceinline__

// ---------------- problem sizes ----------------
static constexpr int M = 8192;
static constexpr int N = 4096;
static constexpr int K = 4096;

// ---------------- GEMM tiling ----------------
static constexpr int BM = 128;
static constexpr int BN = 128;
static constexpr int NCHUNK = K / 32;           // 128 chunks of 32 halves (64 B rows)
static constexpr int NSTAGE = 5;
static constexpr int PITCH = 80;                // 64B row padded -> conflict-free ldmatrix
static constexpr int A_BYTES = BM * PITCH;      // 10240
static constexpr int B_BYTES = BN * PITCH;      // 10240
static constexpr int STAGE_BYTES = A_BYTES + B_BYTES;        // 20480
static constexpr int SMEM_TOTAL = NSTAGE * STAGE_BYTES;      // 102400 -> 2 CTAs/SM

// ---------------- device scratch ----------------
__device__ __half g_xq[(size_t)M * K];          // fp16 quantized activations (exact ints)
__device__ __half g_wq[(size_t)N * K];          // fp16 ternary weights {-1,0,1}
__device__ float  g_sx[M];
__device__ double g_part[4096];
__device__ float  g_sw;
__device__ float  g_wdenom;

// ---------------- helpers ----------------
DI uint32_t smem_u32(const void* p) {
    uint32_t a;
    asm("{ .reg .u64 t; cvta.to.shared.u64 t, %1; cvt.u32.u64 %0, t; }" : "=r"(a) : "l"(p));
    return a;
}
DI void cp16(uint32_t dst, const void* src) {
    asm volatile("cp.async.cg.shared.global [%0], [%1], 16;"
                 :: "r"(dst), "l"(__cvta_generic_to_global(src)) : "memory");
}
DI void cp_commit() { asm volatile("cp.async.commit_group;" ::: "memory"); }
DI void cp_wait3()  { asm volatile("cp.async.wait_group 3;"  ::: "memory"); }

DI void ldsm_x4(uint32_t* r, uint32_t addr) {
    asm volatile("ldmatrix.sync.aligned.m8n8.x4.shared.b16 {%0,%1,%2,%3}, [%4];"
                 : "=r"(r[0]), "=r"(r[1]), "=r"(r[2]), "=r"(r[3]) : "r"(addr));
}
DI void hmma(float* c, const uint32_t* a, uint32_t b0, uint32_t b1) {
    asm volatile(
        "mma.sync.aligned.m16n8k16.row.col.f32.f16.f16.f32 "
        "{%0,%1,%2,%3}, {%4,%5,%6,%7}, {%8,%9}, {%0,%1,%2,%3};"
        : "+f"(c[0]), "+f"(c[1]), "+f"(c[2]), "+f"(c[3])
        : "r"(a[0]), "r"(a[1]), "r"(a[2]), "r"(a[3]), "r"(b0), "r"(b1));
}
DI uint32_t pack_h2(float a, float b) {
    __half2 t = __floats2half2_rn(a, b);
    return *reinterpret_cast<uint32_t*>(&t);
}

// ==================== quantization (R10, unchanged) ====================

__global__ void k_wabs(const float* __restrict__ w) {
    __shared__ double red[256];
    const int row = blockIdx.x;
    const float4* p = reinterpret_cast<const float4*>(w + (size_t)row * 4096);
    float s0 = 0.f, s1 = 0.f, s2 = 0.f, s3 = 0.f;
#pragma unroll
    for (int j = 0; j < 4; ++j) {
        float4 v = p[threadIdx.x + j * 256];
        s0 += fabsf(v.x);
        s1 += fabsf(v.y);
        s2 += fabsf(v.z);
        s3 += fabsf(v.w);
    }
    red[threadIdx.x] = (double)((s0 + s1) + (s2 + s3));
    __syncthreads();
    for (int st = 128; st > 0; st >>= 1) {
        if (threadIdx.x < st) red[threadIdx.x] += red[threadIdx.x + st];
        __syncthreads();
    }
    if (threadIdx.x == 0) g_part[row] = red[0];
}

__global__ void k_wscale() {
    __shared__ double red[256];
    double s = 0.0;
#pragma unroll
    for (int j = 0; j < 16; ++j) s += g_part[threadIdx.x + j * 256];
    red[threadIdx.x] = s;
    __syncthreads();
    for (int st = 128; st > 0; st >>= 1) {
        if (threadIdx.x < st) red[threadIdx.x] += red[threadIdx.x + st];
        __syncthreads();
    }
    if (threadIdx.x == 0) {
        float sc = (float)(red[0] / 16777216.0);
        g_sw = sc;
        g_wdenom = sc + 1e-8f;
    }
}

__global__ void k_wq(const float* __restrict__ w) {
    const size_t i = (size_t)blockIdx.x * 256 + threadIdx.x;
    float4 v = reinterpret_cast<const float4*>(w)[i];
    const float d = g_wdenom;
    float q0 = fminf(fmaxf(rintf(v.x / d), -1.f), 1.f);
    float q1 = fminf(fmaxf(rintf(v.y / d), -1.f), 1.f);
    float q2 = fminf(fmaxf(rintf(v.z / d), -1.f), 1.f);
    float q3 = fminf(fmaxf(rintf(v.w / d), -1.f), 1.f);
    uint2 o;
    o.x = pack_h2(q0, q1);
    o.y = pack_h2(q2, q3);
    reinterpret_cast<uint2*>(g_wq)[i] = o;
}

__global__ void k_xq(const float* __restrict__ x) {
    __shared__ float red[256];
    __shared__ float s_scale;
    const int row = blockIdx.x;
    const float4* p = reinterpret_cast<const float4*>(x + (size_t)row * 4096);
    float4 v[4];
    float am = 0.f;
#pragma unroll
    for (int j = 0; j < 4; ++j) {
        v[j] = p[threadIdx.x + j * 256];
        am = fmaxf(am, fmaxf(fmaxf(fabsf(v[j].x), fabsf(v[j].y)),
                             fmaxf(fabsf(v[j].z), fabsf(v[j].w))));
    }
    red[threadIdx.x] = am;
    __syncthreads();
    for (int st = 128; st > 0; st >>= 1) {
        if (threadIdx.x < st) red[threadIdx.x] = fmaxf(red[threadIdx.x], red[threadIdx.x + st]);
        __syncthreads();
    }
    if (threadIdx.x == 0) {
        float sc = fmaxf(red[0] / 127.0f, 1e-8f);
        s_scale = sc;
        g_sx[row] = sc;
    }
    __syncthreads();
    const float sc = s_scale;
    uint2* out = reinterpret_cast<uint2*>(g_xq + (size_t)row * 4096);
#pragma unroll
    for (int j = 0; j < 4; ++j) {
        float q0 = fminf(fmaxf(rintf(v[j].x / sc), -127.f), 127.f);
        float q1 = fminf(fmaxf(rintf(v[j].y / sc), -127.f), 127.f);
        float q2 = fminf(fmaxf(rintf(v[j].z / sc), -127.f), 127.f);
        float q3 = fminf(fmaxf(rintf(v[j].w / sc), -127.f), 127.f);
        uint2 o;
        o.x = pack_h2(q0, q1);
        o.y = pack_h2(q2, q3);
        out[threadIdx.x + j * 256] = o;
    }
}

// ==================== GEMM ====================
// out[M,N] = g_xq[M,K](f16 ints) . g_wq[N,K](f16 ternary)^T, scaled by sx[m]*sw.
// CTA 128x128x32, 4 warps (2m x 2n), warp tile 64x64 via m16n8k16 HMMA, fp32 acc.
// 5-stage cp.async ring, 2 CTAs/SM (8 warps/SM from independent CTAs).
// Rationale: smem-crossbar-bound; 64x64 warp tiles cut fragment re-reads 96KB->64KB
// per chunk-pair while 2 independent CTAs/SMSP preserve latency hiding.

__global__ void __launch_bounds__(128, 2) k_gemm(float* __restrict__ out) {
    extern __shared__ char smem[];
    const uint32_t sb = smem_u32(smem);
    const int tid = threadIdx.x, wid = tid >> 5, lane = tid & 31;
    const int wm = wid & 1, wn = wid >> 1;      // warp grid 2 (m) x 2 (n)

    const int nt = blockIdx.x & 31;             // n fast-varying: W stays L2-hot
    const int mt = blockIdx.x >> 5;

    const char* gA = (const char*)g_xq + (size_t)mt * BM * K * 2;
    const char* gB = (const char*)g_wq + (size_t)nt * BN * K * 2;

    // cp.async coordinates: 128 threads cover 32 rows x 64B per pass
    const int lr = tid >> 2, lc = tid & 3;

    // ldmatrix per-thread offsets
    const int rowL = lane & 15;
    const int byteL = (lane >> 4) * 16;
    uint32_t aoff[4], boff[4];
#pragma unroll
    for (int im = 0; im < 4; ++im)
        aoff[im] = (uint32_t)((wm * 64 + im * 16 + rowL) * PITCH + byteL);
#pragma unroll
    for (int ib = 0; ib < 4; ++ib)
        boff[ib] = (uint32_t)(A_BYTES + (wn * 64 + ib * 16 + rowL) * PITCH + byteL);

    float acc[4][8][4];
#pragma unroll
    for (int i = 0; i < 4; ++i)
#pragma unroll
        for (int j = 0; j < 8; ++j)
#pragma unroll
            for (int q = 0; q < 4; ++q) acc[i][j][q] = 0.f;

    auto load_stage = [&](int stage, int kc) {
        const uint32_t base = sb + stage * STAGE_BYTES;
        const size_t koff = (size_t)kc * 64;
#pragma unroll
        for (int i = 0; i < 4; ++i) {            // A: 128 rows
            const int r = lr + i * 32;
            cp16(base + r * PITCH + lc * 16, gA + (size_t)r * 8192 + koff + lc * 16);
        }
#pragma unroll
        for (int i = 0; i < 4; ++i) {            // B: 128 rows
            const int r = lr + i * 32;
            cp16(base + A_BYTES + r * PITCH + lc * 16, gB + (size_t)r * 8192 + koff + lc * 16);
        }
    };

#pragma unroll
    for (int s = 0; s < NSTAGE - 1; ++s) { load_stage(s, s); cp_commit(); }

    int rd = 0, wr = NSTAGE - 1;
    for (int kc = 0; kc < NCHUNK; ++kc) {
        cp_wait3();
        __syncthreads();

        if (kc + NSTAGE - 1 < NCHUNK) load_stage(wr, kc + NSTAGE - 1);
        cp_commit();

        const uint32_t stage_base = sb + rd * STAGE_BYTES;
#pragma unroll
        for (int ks = 0; ks < 2; ++ks) {
            uint32_t a[4][4], b[4][4];
#pragma unroll
            for (int im = 0; im < 4; ++im) ldsm_x4(a[im], stage_base + aoff[im] + ks * 32);
#pragma unroll
            for (int ib = 0; ib < 4; ++ib) ldsm_x4(b[ib], stage_base + boff[ib] + ks * 32);
#pragma unroll
            for (int im = 0; im < 4; ++im) {
#pragma unroll
                for (int in = 0; in < 8; ++in) {
                    const int ib = in >> 1, od = in & 1;
                    hmma(acc[im][in], a[im], b[ib][od ? 1 : 0], b[ib][od ? 3 : 2]);
                }
            }
        }
        rd = (rd == NSTAGE - 1) ? 0 : rd + 1;
        wr = (wr == NSTAGE - 1) ? 0 : wr + 1;
    }

    // ---- epilogue: scale by sx[row]*sw and store ----
    const float swv = g_sw;
    const int row0 = mt * BM + wm * 64 + (lane >> 2);
    const int col0 = nt * BN + wn * 64 + 2 * (lane & 3);
#pragma unroll
    for (int im = 0; im < 4; ++im) {
        const int r = row0 + im * 16;
        const float f0 = g_sx[r] * swv;
        const float f8 = g_sx[r + 8] * swv;
        float* po0 = out + (size_t)r * N + col0;
        float* po8 = out + (size_t)(r + 8) * N + col0;
#pragma unroll
        for (int in = 0; in < 8; ++in) {
            float2 v0, v8;
            v0.x = acc[im][in][0] * f0;
            v0.y = acc[im][in][1] * f0;
            v8.x = acc[im][in][2] * f8;
            v8.y = acc[im][in][3] * f8;
            *reinterpret_cast<float2*>(po0 + in * 8) = v0;
            *reinterpret_cast<float2*>(po8 + in * 8) = v8;
        }
    }
}

// ==================== launch ====================
extern "C" void kernel_launch(void* const* d_in, const int* in_sizes, int n_in,
                              void* d_out, int out_size) {
    const float* x = (const float*)d_in[0];
    const float* w = (const float*)d_in[1];
    float* out = (float*)d_out;
    (void)in_sizes; (void)n_in; (void)out_size;

    k_wabs<<<4096, 256>>>(w);
    k_wscale<<<1, 256>>>();
    k_wq<<<16384, 256>>>(w);
    k_xq<<<8192, 256>>>(x);

    cudaFuncSetAttribute(k_gemm, cudaFuncAttributeMaxDynamicSharedMemorySize, SMEM_TOTAL);
    k_gemm<<<(M / BM) * (N / BN), 128, SMEM_TOTAL>>>(out);
}

// round 12
// speedup vs baseline: 1.1220x; 1.1220x over previous
#include <cuda_runtime.h>
#include <cuda_fp16.h>
#include <cstdint>

#define DI __device__ __forceinline__

// ---------------- problem sizes ----------------
static constexpr int M = 8192;
static constexpr int N = 4096;
static constexpr int K = 4096;

// ---------------- GEMM tiling (R8/R10 shape — best known) ----------------
static constexpr int BM = 128;
static constexpr int BN = 128;
static constexpr int NCHUNK = K / 32;           // 128 chunks of 32 halves (64 B rows)
static constexpr int NSTAGE = 5;
static constexpr int PITCH = 80;                // 64B row padded -> conflict-free ldmatrix
static constexpr int A_BYTES = BM * PITCH;      // 10240
static constexpr int B_BYTES = BN * PITCH;      // 10240
static constexpr int STAGE_BYTES = A_BYTES + B_BYTES;        // 20480
static constexpr int SMEM_TOTAL = NSTAGE * STAGE_BYTES;      // 102400 -> 2 CTAs/SM

// ---------------- device scratch ----------------
__device__ __half g_xq[(size_t)M * K];          // fp16 quantized activations (exact ints)
__device__ __half g_wq[(size_t)N * K];          // fp16 ternary weights {-1,0,1}
__device__ float  g_sx[M];
__device__ double g_part[4096];
__device__ float  g_sw;
__device__ float  g_wdenom;

// ---------------- helpers ----------------
DI uint32_t smem_u32(const void* p) {
    uint32_t a;
    asm("{ .reg .u64 t; cvta.to.shared.u64 t, %1; cvt.u32.u64 %0, t; }" : "=r"(a) : "l"(p));
    return a;
}
DI void cp16(uint32_t dst, const void* src) {
    asm volatile("cp.async.cg.shared.global [%0], [%1], 16;"
                 :: "r"(dst), "l"(__cvta_generic_to_global(src)) : "memory");
}
DI void cp_commit() { asm volatile("cp.async.commit_group;" ::: "memory"); }
DI void cp_wait3()  { asm volatile("cp.async.wait_group 3;"  ::: "memory"); }

DI void ldsm_x4(uint32_t* r, uint32_t addr) {
    asm volatile("ldmatrix.sync.aligned.m8n8.x4.shared.b16 {%0,%1,%2,%3}, [%4];"
                 : "=r"(r[0]), "=r"(r[1]), "=r"(r[2]), "=r"(r[3]) : "r"(addr));
}
DI void hmma(float* c, const uint32_t* a, uint32_t b0, uint32_t b1) {
    asm volatile(
        "mma.sync.aligned.m16n8k16.row.col.f32.f16.f16.f32 "
        "{%0,%1,%2,%3}, {%4,%5,%6,%7}, {%8,%9}, {%0,%1,%2,%3};"
        : "+f"(c[0]), "+f"(c[1]), "+f"(c[2]), "+f"(c[3])
        : "r"(a[0]), "r"(a[1]), "r"(a[2]), "r"(a[3]), "r"(b0), "r"(b1));
}
DI uint32_t pack_h2(float a, float b) {
    __half2 t = __floats2half2_rn(a, b);
    return *reinterpret_cast<uint32_t*>(&t);
}

// ==================== merged quant stage 1: wabs (blocks 0..4095) || xq (blocks 4096..12287) ====================

__global__ void k_prep(const float* __restrict__ w, const float* __restrict__ x) {
    if (blockIdx.x < 4096) {
        // ---- W row |abs| sum (fp32 partials, fp64 tree) ----
        __shared__ double redd[256];
        const int row = blockIdx.x;
        const float4* p = reinterpret_cast<const float4*>(w + (size_t)row * 4096);
        float s0 = 0.f, s1 = 0.f, s2 = 0.f, s3 = 0.f;
#pragma unroll
        for (int j = 0; j < 4; ++j) {
            float4 v = p[threadIdx.x + j * 256];
            s0 += fabsf(v.x);
            s1 += fabsf(v.y);
            s2 += fabsf(v.z);
            s3 += fabsf(v.w);
        }
        redd[threadIdx.x] = (double)((s0 + s1) + (s2 + s3));
        __syncthreads();
        for (int st = 128; st > 0; st >>= 1) {
            if (threadIdx.x < st) redd[threadIdx.x] += redd[threadIdx.x + st];
            __syncthreads();
        }
        if (threadIdx.x == 0) g_part[row] = redd[0];
    } else {
        // ---- X row absmax int8 fake-quant -> fp16 ints ----
        __shared__ float red[256];
        __shared__ float s_scale;
        const int row = blockIdx.x - 4096;
        const float4* p = reinterpret_cast<const float4*>(x + (size_t)row * 4096);
        float4 v[4];
        float am = 0.f;
#pragma unroll
        for (int j = 0; j < 4; ++j) {
            v[j] = p[threadIdx.x + j * 256];
            am = fmaxf(am, fmaxf(fmaxf(fabsf(v[j].x), fabsf(v[j].y)),
                                 fmaxf(fabsf(v[j].z), fabsf(v[j].w))));
        }
        red[threadIdx.x] = am;
        __syncthreads();
        for (int st = 128; st > 0; st >>= 1) {
            if (threadIdx.x < st) red[threadIdx.x] = fmaxf(red[threadIdx.x], red[threadIdx.x + st]);
            __syncthreads();
        }
        if (threadIdx.x == 0) {
            float sc = fmaxf(red[0] / 127.0f, 1e-8f);
            s_scale = sc;
            g_sx[row] = sc;
        }
        __syncthreads();
        const float sc = s_scale;
        uint2* out = reinterpret_cast<uint2*>(g_xq + (size_t)row * 4096);
#pragma unroll
        for (int j = 0; j < 4; ++j) {
            float q0 = fminf(fmaxf(rintf(v[j].x / sc), -127.f), 127.f);
            float q1 = fminf(fmaxf(rintf(v[j].y / sc), -127.f), 127.f);
            float q2 = fminf(fmaxf(rintf(v[j].z / sc), -127.f), 127.f);
            float q3 = fminf(fmaxf(rintf(v[j].w / sc), -127.f), 127.f);
            uint2 o;
            o.x = pack_h2(q0, q1);
            o.y = pack_h2(q2, q3);
            out[threadIdx.x + j * 256] = o;
        }
    }
}

__global__ void k_wscale() {
    __shared__ double red[256];
    double s = 0.0;
#pragma unroll
    for (int j = 0; j < 16; ++j) s += g_part[threadIdx.x + j * 256];
    red[threadIdx.x] = s;
    __syncthreads();
    for (int st = 128; st > 0; st >>= 1) {
        if (threadIdx.x < st) red[threadIdx.x] += red[threadIdx.x + st];
        __syncthreads();
    }
    if (threadIdx.x == 0) {
        float sc = (float)(red[0] / 16777216.0);
        g_sw = sc;
        g_wdenom = sc + 1e-8f;
    }
}

__global__ void k_wq(const float* __restrict__ w) {
    const size_t i = (size_t)blockIdx.x * 256 + threadIdx.x;
    float4 v = reinterpret_cast<const float4*>(w)[i];
    const float d = g_wdenom;
    float q0 = fminf(fmaxf(rintf(v.x / d), -1.f), 1.f);
    float q1 = fminf(fmaxf(rintf(v.y / d), -1.f), 1.f);
    float q2 = fminf(fmaxf(rintf(v.z / d), -1.f), 1.f);
    float q3 = fminf(fmaxf(rintf(v.w / d), -1.f), 1.f);
    uint2 o;
    o.x = pack_h2(q0, q1);
    o.y = pack_h2(q2, q3);
    reinterpret_cast<uint2*>(g_wq)[i] = o;
}

// ==================== GEMM (R8, unchanged — best known) ====================
// out[M,N] = g_xq[M,K](f16 ints) . g_wq[N,K](f16 ternary)^T, scaled by sx[m]*sw.
// CTA 128x128x32, 8 warps (2m x 4n), warp tile 64x32 via m16n8k16 HMMA, fp32 acc.
// 5-stage cp.async ring, 2 CTAs/SM (16 warps/SM, 4/SMSP).

__global__ void __launch_bounds__(256, 2) k_gemm(float* __restrict__ out) {
    extern __shared__ char smem[];
    const uint32_t sb = smem_u32(smem);
    const int tid = threadIdx.x, wid = tid >> 5, lane = tid & 31;
    const int wm = wid & 1, wn = wid >> 1;      // warp grid 2 (m) x 4 (n)

    const int nt = blockIdx.x & 31;             // n fast-varying: W stays L2-hot
    const int mt = blockIdx.x >> 5;

    const char* gA = (const char*)g_xq + (size_t)mt * BM * K * 2;
    const char* gB = (const char*)g_wq + (size_t)nt * BN * K * 2;

    const int lr = tid >> 2, lc = tid & 3;

    const int rowL = lane & 15;
    const int byteL = (lane >> 4) * 16;
    uint32_t aoff[4], boff[2];
#pragma unroll
    for (int im = 0; im < 4; ++im)
        aoff[im] = (uint32_t)((wm * 64 + im * 16 + rowL) * PITCH + byteL);
#pragma unroll
    for (int ib = 0; ib < 2; ++ib)
        boff[ib] = (uint32_t)(A_BYTES + (wn * 32 + ib * 16 + rowL) * PITCH + byteL);

    float acc[4][4][4];
#pragma unroll
    for (int i = 0; i < 4; ++i)
#pragma unroll
        for (int j = 0; j < 4; ++j)
#pragma unroll
            for (int q = 0; q < 4; ++q) acc[i][j][q] = 0.f;

    auto load_stage = [&](int stage, int kc) {
        const uint32_t base = sb + stage * STAGE_BYTES;
        const size_t koff = (size_t)kc * 64;
#pragma unroll
        for (int i = 0; i < 2; ++i) {
            const int r = lr + i * 64;
            cp16(base + r * PITCH + lc * 16, gA + (size_t)r * 8192 + koff + lc * 16);
        }
#pragma unroll
        for (int i = 0; i < 2; ++i) {
            const int r = lr + i * 64;
            cp16(base + A_BYTES + r * PITCH + lc * 16, gB + (size_t)r * 8192 + koff + lc * 16);
        }
    };

#pragma unroll
    for (int s = 0; s < NSTAGE - 1; ++s) { load_stage(s, s); cp_commit(); }

    int rd = 0, wr = NSTAGE - 1;
    for (int kc = 0; kc < NCHUNK; ++kc) {
        cp_wait3();
        __syncthreads();

        if (kc + NSTAGE - 1 < NCHUNK) load_stage(wr, kc + NSTAGE - 1);
        cp_commit();

        const uint32_t stage_base = sb + rd * STAGE_BYTES;
#pragma unroll
        for (int ks = 0; ks < 2; ++ks) {
            uint32_t a[4][4], b[2][4];
#pragma unroll
            for (int im = 0; im < 4; ++im) ldsm_x4(a[im], stage_base + aoff[im] + ks * 32);
#pragma unroll
            for (int ib = 0; ib < 2; ++ib) ldsm_x4(b[ib], stage_base + boff[ib] + ks * 32);
#pragma unroll
            for (int im = 0; im < 4; ++im) {
#pragma unroll
                for (int in = 0; in < 4; ++in) {
                    const int ib = in >> 1, od = in & 1;
                    hmma(acc[im][in], a[im], b[ib][od ? 1 : 0], b[ib][od ? 3 : 2]);
                }
            }
        }
        rd = (rd == NSTAGE - 1) ? 0 : rd + 1;
        wr = (wr == NSTAGE - 1) ? 0 : wr + 1;
    }

    // ---- epilogue: scale by sx[row]*sw and store ----
    const float swv = g_sw;
    const int row0 = mt * BM + wm * 64 + (lane >> 2);
    const int col0 = nt * BN + wn * 32 + 2 * (lane & 3);
#pragma unroll
    for (int im = 0; im < 4; ++im) {
        const int r = row0 + im * 16;
        const float f0 = g_sx[r] * swv;
        const float f8 = g_sx[r + 8] * swv;
        float* po0 = out + (size_t)r * N + col0;
        float* po8 = out + (size_t)(r + 8) * N + col0;
#pragma unroll
        for (int in = 0; in < 4; ++in) {
            float2 v0, v8;
            v0.x = acc[im][in][0] * f0;
            v0.y = acc[im][in][1] * f0;
            v8.x = acc[im][in][2] * f8;
            v8.y = acc[im][in][3] * f8;
            *reinterpret_cast<float2*>(po0 + in * 8) = v0;
            *reinterpret_cast<float2*>(po8 + in * 8) = v8;
        }
    }
}

// ==================== launch ====================
extern "C" void kernel_launch(void* const* d_in, const int* in_sizes, int n_in,
                              void* d_out, int out_size) {
    const float* x = (const float*)d_in[0];
    const float* w = (const float*)d_in[1];
    float* out = (float*)d_out;
    (void)in_sizes; (void)n_in; (void)out_size;

    k_prep<<<4096 + 8192, 256>>>(w, x);     // wabs (W rows) || xq (X rows), independent work
    k_wscale<<<1, 256>>>();
    k_wq<<<16384, 256>>>(w);

    cudaFuncSetAttribute(k_gemm, cudaFuncAttributeMaxDynamicSharedMemorySize, SMEM_TOTAL);
    k_gemm<<<(M / BM) * (N / BN), 256, SMEM_TOTAL>>>(out);
}